// round 1
// baseline (speedup 1.0000x reference)
#include <cuda_runtime.h>
#include <math.h>

// Problem constants
#define BB 16
#define LL 1024
#define DD 256
#define HH 256
#define KW 16
#define MM (BB * LL)      // 16384
#define G3 (3 * HH)       // 768

// Scratch (device globals: allocation-free rule)
__device__ float g_Gx[(size_t)MM * G3];        // x @ W_ih^T + b_ih  (~50 MB)
__device__ float g_H[2][(size_t)MM * HH];      // ping-pong hidden state (2 x ~17 MB)

// ---------------------------------------------------------------------------
// Kernel 1: Gx[m, n] = sum_d x[m,d] * W_ih[n,d] + b_ih[n]
// Tile: 64 rows x 64 cols, BK=16, 256 threads, 4x4 microtile.
// ---------------------------------------------------------------------------
__global__ __launch_bounds__(256) void gx_kernel(const float* __restrict__ x,
                                                 const float* __restrict__ W_ih,
                                                 const float* __restrict__ b_ih)
{
    __shared__ float As[16][64];   // [k][row]
    __shared__ float Bs[16][64];   // [k][col]

    const int m0 = blockIdx.y * 64;
    const int n0 = blockIdx.x * 64;
    const int tid = threadIdx.x;
    const int lrow = tid >> 2;          // 0..63
    const int lkq  = (tid & 3) * 4;     // 0,4,8,12
    const int tx = tid & 15;            // col group
    const int ty = tid >> 4;            // row group

    float acc[4][4] = {};

    for (int k0 = 0; k0 < DD; k0 += 16) {
        float4 av = *(const float4*)&x[(size_t)(m0 + lrow) * DD + k0 + lkq];
        float4 bv = *(const float4*)&W_ih[(size_t)(n0 + lrow) * DD + k0 + lkq];
        __syncthreads();
        As[lkq + 0][lrow] = av.x; As[lkq + 1][lrow] = av.y;
        As[lkq + 2][lrow] = av.z; As[lkq + 3][lrow] = av.w;
        Bs[lkq + 0][lrow] = bv.x; Bs[lkq + 1][lrow] = bv.y;
        Bs[lkq + 2][lrow] = bv.z; Bs[lkq + 3][lrow] = bv.w;
        __syncthreads();

        #pragma unroll
        for (int kk = 0; kk < 16; kk++) {
            float4 a4 = *(const float4*)&As[kk][ty * 4];
            float4 b4 = *(const float4*)&Bs[kk][tx * 4];
            acc[0][0] += a4.x * b4.x; acc[0][1] += a4.x * b4.y;
            acc[0][2] += a4.x * b4.z; acc[0][3] += a4.x * b4.w;
            acc[1][0] += a4.y * b4.x; acc[1][1] += a4.y * b4.y;
            acc[1][2] += a4.y * b4.z; acc[1][3] += a4.y * b4.w;
            acc[2][0] += a4.z * b4.x; acc[2][1] += a4.z * b4.y;
            acc[2][2] += a4.z * b4.z; acc[2][3] += a4.z * b4.w;
            acc[3][0] += a4.w * b4.x; acc[3][1] += a4.w * b4.y;
            acc[3][2] += a4.w * b4.z; acc[3][3] += a4.w * b4.w;
        }
    }

    #pragma unroll
    for (int i = 0; i < 4; i++) {
        int m = m0 + ty * 4 + i;
        #pragma unroll
        for (int j = 0; j < 4; j++) {
            int n = n0 + tx * 4 + j;
            g_Gx[(size_t)m * G3 + n] = acc[i][j] + b_ih[n];
        }
    }
}

// ---------------------------------------------------------------------------
// Kernel 2: one GRU window-step (fused GEMM + gate epilogue)
//   GH = Hin @ W_hh^T ; gates from Gx (shifted by t) ; Hout = GRU update
// Tile: 64 rows x 64 h-cols (=> 192 gate-cols), BK=16, 256 threads,
//       4x4 microtile x 3 gates = 48 accumulators.
// ---------------------------------------------------------------------------
__global__ __launch_bounds__(256) void step_kernel(const float* __restrict__ W_hh,
                                                   const float* __restrict__ b_ih,
                                                   const float* __restrict__ b_hh,
                                                   int t, int zero_h, int src,
                                                   float* __restrict__ ext_out)
{
    __shared__ float As[16][64];        // H tile [k][row]
    __shared__ float Bs[3][16][64];     // W_hh tiles per gate [k][col]

    const float* __restrict__ Hin = g_H[src];
    float* __restrict__ Hout = ext_out ? ext_out : g_H[src ^ 1];

    const int m0 = blockIdx.y * 64;
    const int c0 = blockIdx.x * 64;
    const int tid = threadIdx.x;
    const int lrow = tid >> 2;
    const int lkq  = (tid & 3) * 4;
    const int tx = tid & 15;
    const int ty = tid >> 4;

    float acc[3][4][4] = {};

    if (!zero_h) {
        for (int k0 = 0; k0 < HH; k0 += 16) {
            float4 av = *(const float4*)&Hin[(size_t)(m0 + lrow) * HH + k0 + lkq];
            float4 bv0 = *(const float4*)&W_hh[(size_t)(0 * HH + c0 + lrow) * HH + k0 + lkq];
            float4 bv1 = *(const float4*)&W_hh[(size_t)(1 * HH + c0 + lrow) * HH + k0 + lkq];
            float4 bv2 = *(const float4*)&W_hh[(size_t)(2 * HH + c0 + lrow) * HH + k0 + lkq];
            __syncthreads();
            As[lkq + 0][lrow] = av.x; As[lkq + 1][lrow] = av.y;
            As[lkq + 2][lrow] = av.z; As[lkq + 3][lrow] = av.w;
            Bs[0][lkq + 0][lrow] = bv0.x; Bs[0][lkq + 1][lrow] = bv0.y;
            Bs[0][lkq + 2][lrow] = bv0.z; Bs[0][lkq + 3][lrow] = bv0.w;
            Bs[1][lkq + 0][lrow] = bv1.x; Bs[1][lkq + 1][lrow] = bv1.y;
            Bs[1][lkq + 2][lrow] = bv1.z; Bs[1][lkq + 3][lrow] = bv1.w;
            Bs[2][lkq + 0][lrow] = bv2.x; Bs[2][lkq + 1][lrow] = bv2.y;
            Bs[2][lkq + 2][lrow] = bv2.z; Bs[2][lkq + 3][lrow] = bv2.w;
            __syncthreads();

            #pragma unroll
            for (int kk = 0; kk < 16; kk++) {
                float4 a4 = *(const float4*)&As[kk][ty * 4];
                #pragma unroll
                for (int g = 0; g < 3; g++) {
                    float4 b4 = *(const float4*)&Bs[g][kk][tx * 4];
                    acc[g][0][0] += a4.x * b4.x; acc[g][0][1] += a4.x * b4.y;
                    acc[g][0][2] += a4.x * b4.z; acc[g][0][3] += a4.x * b4.w;
                    acc[g][1][0] += a4.y * b4.x; acc[g][1][1] += a4.y * b4.y;
                    acc[g][1][2] += a4.y * b4.z; acc[g][1][3] += a4.y * b4.w;
                    acc[g][2][0] += a4.z * b4.x; acc[g][2][1] += a4.z * b4.y;
                    acc[g][2][2] += a4.z * b4.z; acc[g][2][3] += a4.z * b4.w;
                    acc[g][3][0] += a4.w * b4.x; acc[g][3][1] += a4.w * b4.y;
                    acc[g][3][2] += a4.w * b4.z; acc[g][3][3] += a4.w * b4.w;
                }
            }
        }
    }

    // GRU epilogue
    #pragma unroll
    for (int i = 0; i < 4; i++) {
        int m = m0 + ty * 4 + i;
        int l = m & (LL - 1);
        int p = l - (KW - 1) + t;     // window input position within the sequence
        const float* __restrict__ gx =
            (p >= 0) ? &g_Gx[(size_t)(m - (KW - 1) + t) * G3] : nullptr;
        #pragma unroll
        for (int j = 0; j < 4; j++) {
            int c = c0 + tx * 4 + j;
            float gi_r, gi_z, gi_n;
            if (gx) {
                gi_r = gx[c];
                gi_z = gx[HH + c];
                gi_n = gx[2 * HH + c];
            } else {              // x = 0 (left pad) -> gi = b_ih
                gi_r = b_ih[c];
                gi_z = b_ih[HH + c];
                gi_n = b_ih[2 * HH + c];
            }
            float gh_r = acc[0][i][j] + b_hh[c];
            float gh_z = acc[1][i][j] + b_hh[HH + c];
            float gh_n = acc[2][i][j] + b_hh[2 * HH + c];
            float hprev = zero_h ? 0.0f : Hin[(size_t)m * HH + c];
            float r = 1.0f / (1.0f + expf(-(gi_r + gh_r)));
            float z = 1.0f / (1.0f + expf(-(gi_z + gh_z)));
            float n = tanhf(gi_n + r * gh_n);
            Hout[(size_t)m * HH + c] = (1.0f - z) * n + z * hprev;
        }
    }
}

// ---------------------------------------------------------------------------
extern "C" void kernel_launch(void* const* d_in, const int* in_sizes, int n_in,
                              void* d_out, int out_size)
{
    const float* x    = (const float*)d_in[0];
    const float* W_ih = (const float*)d_in[1];
    const float* W_hh = (const float*)d_in[2];
    const float* b_ih = (const float*)d_in[3];
    const float* b_hh = (const float*)d_in[4];
    float* out = (float*)d_out;

    // 1) Input-gate precompute: Gx = x @ W_ih^T + b_ih
    gx_kernel<<<dim3(G3 / 64, MM / 64), 256>>>(x, W_ih, b_ih);

    // 2) 16 fused GEMM+GRU window steps (step 0 skips the GEMM: h=0)
    for (int t = 0; t < KW; t++) {
        int zero_h = (t == 0) ? 1 : 0;
        int src = (t + 1) & 1;                         // step t reads g_H[(t+1)&1], writes g_H[t&1]
        float* ext = (t == KW - 1) ? out : nullptr;    // last step writes d_out directly
        step_kernel<<<dim3(HH / 64, MM / 64), 256>>>(W_hh, b_ih, b_hh,
                                                     t, zero_h, src, ext);
    }
}

// round 3
// speedup vs baseline: 2.4751x; 2.4751x over previous
#include <cuda_runtime.h>
#include <cuda_fp16.h>
#include <cstdint>
#include <math.h>

// ---------------------------------------------------------------------------
// Problem constants
// ---------------------------------------------------------------------------
#define MM 16384          // B*L
#define KW 16             // window
#define NKC 8             // K chunks of 64 halfs (K = 512 = 256 hi/lo pairs)

// ---------------------------------------------------------------------------
// Device scratch (allocation-free rule: device globals)
// ---------------------------------------------------------------------------
__device__ unsigned int g_xp[(size_t)MM * 256];       // x as (hi,lo) fp16 pairs
__device__ unsigned int g_Hp[2][(size_t)MM * 256];    // hidden state ping-pong
__device__ float g_Gx[(size_t)MM * 768];              // x@W_ih^T + b_ih (gate-major packed cols)
__device__ __half g_Wgx[8 * 96 * 512];                // W_ih packed [ct][96][512] (rows duplicated along k)
__device__ __half g_Wst[8 * 96 * 512];                // W_hh packed likewise

#define SWZ(o) ((o) ^ (((o) >> 3) & 0x70))

// ---------------------------------------------------------------------------
// PTX helpers
// ---------------------------------------------------------------------------
__device__ __forceinline__ uint32_t smem_u32(const void* p) {
    uint32_t a;
    asm("{ .reg .u64 t; cvta.to.shared.u64 t, %1; cvt.u32.u64 %0, t; }"
        : "=r"(a) : "l"(p));
    return a;
}
__device__ __forceinline__ void cp16(uint32_t d, const void* s) {
    asm volatile("cp.async.cg.shared.global [%0], [%1], 16;"
                 :: "r"(d), "l"(s) : "memory");
}
__device__ __forceinline__ void cp_commit() { asm volatile("cp.async.commit_group;" ::: "memory"); }
__device__ __forceinline__ void cp_wait1()  { asm volatile("cp.async.wait_group 1;" ::: "memory"); }
__device__ __forceinline__ void cp_wait0()  { asm volatile("cp.async.wait_group 0;" ::: "memory"); }

__device__ __forceinline__ void ldm4(uint32_t a, uint32_t* r) {
    asm volatile("ldmatrix.sync.aligned.m8n8.x4.shared.b16 {%0,%1,%2,%3}, [%4];"
                 : "=r"(r[0]), "=r"(r[1]), "=r"(r[2]), "=r"(r[3]) : "r"(a));
}
__device__ __forceinline__ void mma16816(float* c, const uint32_t* a, const uint32_t* b) {
    asm volatile("mma.sync.aligned.m16n8k16.row.col.f32.f16.f16.f32 "
                 "{%0,%1,%2,%3}, {%4,%5,%6,%7}, {%8,%9}, {%0,%1,%2,%3};"
                 : "+f"(c[0]), "+f"(c[1]), "+f"(c[2]), "+f"(c[3])
                 : "r"(a[0]), "r"(a[1]), "r"(a[2]), "r"(a[3]), "r"(b[0]), "r"(b[1]));
}

// fp32 -> fp16 hi/lo pair packed in a uint (hi in low half = even k index)
__device__ __forceinline__ unsigned int packh(float f) {
    __half h = __float2half(f);
    __half l = __float2half(f - __half2float(h));
    return (unsigned int)__half_as_ushort(h) | ((unsigned int)__half_as_ushort(l) << 16);
}
__device__ __forceinline__ float unpackh(unsigned int v) {
    return __half2float(__ushort_as_half((unsigned short)(v & 0xffff))) +
           __half2float(__ushort_as_half((unsigned short)(v >> 16)));
}

// ---------------------------------------------------------------------------
// Prep kernels
// ---------------------------------------------------------------------------
__global__ void pack_x_kernel(const float* __restrict__ x) {
    size_t i = (size_t)blockIdx.x * 256 + threadIdx.x;
    g_xp[i] = packh(x[i]);
}

// Packed weights: [ct][row=g*32+c][k], k=2j and 2j+1 both hold W[g*256+ct*32+c][j]
__global__ void pack_w_kernel(const float* __restrict__ W_ih,
                              const float* __restrict__ W_hh) {
    int idx = blockIdx.x * 256 + threadIdx.x;        // < 8*96*512
    int k = idx & 511;
    int r2 = idx >> 9;
    int row = r2 % 96;
    int ct = r2 / 96;
    int g = row >> 5, c = row & 31;
    int j = k >> 1;
    int widx = (g * 256 + ct * 32 + c) * 256 + j;
    g_Wgx[idx] = __float2half(W_ih[widx]);
    g_Wst[idx] = __float2half(W_hh[widx]);
}

// ---------------------------------------------------------------------------
// Step 0 (h = 0): pure elementwise
// ---------------------------------------------------------------------------
__global__ void step0_kernel(const float* __restrict__ b_ih,
                             const float* __restrict__ b_hh) {
    int idx = blockIdx.x * 256 + threadIdx.x;
    int m = idx >> 8, cg = idx & 255;
    int ct = cg >> 5, c = cg & 31;
    int l = m & 1023;
    float gir, giz, gin;
    if (l - (KW - 1) >= 0) {
        const float* gx = &g_Gx[(size_t)(m - (KW - 1)) * 768 + ct * 96];
        gir = gx[c]; giz = gx[32 + c]; gin = gx[64 + c];
    } else {
        gir = b_ih[ct * 32 + c];
        giz = b_ih[256 + ct * 32 + c];
        gin = b_ih[512 + ct * 32 + c];
    }
    float r = 1.f / (1.f + __expf(-(gir + b_hh[ct * 32 + c])));
    float z = 1.f / (1.f + __expf(-(giz + b_hh[256 + ct * 32 + c])));
    float n = tanhf(fmaf(r, b_hh[512 + ct * 32 + c], gin));
    g_Hp[0][idx] = packh((1.f - z) * n);
}

// ---------------------------------------------------------------------------
// Fused GEMM (mma.sync fp16 -> fp32) + epilogue
//   mode 0: Gx = x @ W_ih^T + b_ih   (store to g_Gx, gate-major packed cols)
//   mode 1: gh = h @ W_hh^T, then full GRU gate update
// CTA: 128 M-rows x 96 N-cols (3 gates x 32 h-cols), K=512.
// 8 warps, warp tile 16M x 96N => all 3 gates in-register per lane.
// ---------------------------------------------------------------------------
__global__ void __launch_bounds__(256, 2)
gemm_fused(int mode, int t, int src, int dst,
           const float* __restrict__ b_ih, const float* __restrict__ b_hh,
           float* __restrict__ fout)
{
    extern __shared__ char smem[];
    const int tid = threadIdx.x, wid = tid >> 5, lane = tid & 31;
    const int ct = blockIdx.x;
    const int m0 = blockIdx.y * 128;
    const uint32_t sb = smem_u32(smem);

    const unsigned int* __restrict__ A = (mode == 0) ? g_xp : g_Hp[src];
    const __half* __restrict__ B = (mode == 0) ? g_Wgx : g_Wst;

    float acc[12][4];
    #pragma unroll
    for (int i = 0; i < 12; i++)
        #pragma unroll
        for (int j = 0; j < 4; j++) acc[i][j] = 0.f;

    const char* Abase = (const char*)(A + (size_t)m0 * 256);        // 1024 B/row
    const char* Bbase = (const char*)(B + (size_t)ct * 96 * 512);   // 1024 B/row

    // double-buffered cp.async pipeline over 8 k-chunks (64 halfs each)
    auto load_chunk = [&](int kc, int buf) {
        uint32_t abuf = sb + buf * 16384;
        uint32_t bbuf = sb + 32768 + buf * 12288;
        #pragma unroll
        for (int r = 0; r < 4; r++) {               // A: 128 rows x 8 units
            int idx = tid + 256 * r;
            int row = idx >> 3, u = idx & 7;
            cp16(abuf + SWZ(row * 128 + u * 16),
                 Abase + (size_t)row * 1024 + kc * 128 + u * 16);
        }
        #pragma unroll
        for (int r = 0; r < 3; r++) {               // B: 96 rows x 8 units
            int idx = tid + 256 * r;
            int row = idx >> 3, u = idx & 7;
            cp16(bbuf + SWZ(row * 128 + u * 16),
                 Bbase + (size_t)row * 1024 + kc * 128 + u * 16);
        }
        cp_commit();
    };

    load_chunk(0, 0);
    #pragma unroll 1
    for (int kc = 0; kc < NKC; kc++) {
        if (kc + 1 < NKC) { load_chunk(kc + 1, (kc + 1) & 1); cp_wait1(); }
        else              { cp_wait0(); }
        __syncthreads();
        uint32_t abuf = sb + (kc & 1) * 16384;
        uint32_t bbuf = sb + 32768 + (kc & 1) * 12288;
        #pragma unroll
        for (int ks = 0; ks < 4; ks++) {
            uint32_t af[4];
            {
                int row = wid * 16 + (lane & 15);
                int colb = ks * 32 + ((lane >> 4) << 4);
                ldm4(abuf + SWZ(row * 128 + colb), af);
            }
            #pragma unroll
            for (int p = 0; p < 6; p++) {           // 12 n-blocks, 2 per ldmatrix.x4
                uint32_t bf[4];
                int n = p * 16 + (lane & 7) + ((lane >> 4) << 3);
                int colb = ks * 32 + (((lane >> 3) & 1) << 4);
                ldm4(bbuf + SWZ(n * 128 + colb), bf);
                mma16816(acc[p * 2 + 0], af, bf + 0);
                mma16816(acc[p * 2 + 1], af, bf + 2);
            }
        }
        __syncthreads();
    }

    // ---------------- epilogue (all in registers) ----------------
    const int gid = lane >> 2, tid2 = lane & 3;

    if (mode == 0) {
        #pragma unroll
        for (int i = 0; i < 2; i++) {
            int m = m0 + wid * 16 + gid + i * 8;
            #pragma unroll
            for (int nb = 0; nb < 12; nb++) {
                int g = nb >> 2, cb = nb & 3;
                #pragma unroll
                for (int j = 0; j < 2; j++) {
                    int c = cb * 8 + tid2 * 2 + j;
                    g_Gx[(size_t)m * 768 + ct * 96 + g * 32 + c] =
                        acc[nb][i * 2 + j] + b_ih[g * 256 + ct * 32 + c];
                }
            }
        }
    } else {
        unsigned int* __restrict__ Hdst = g_Hp[dst];
        #pragma unroll
        for (int i = 0; i < 2; i++) {
            int m = m0 + wid * 16 + gid + i * 8;
            int l = m & 1023;
            bool valid = (l - (KW - 1) + t) >= 0;
            const float* gx = &g_Gx[(size_t)(m - (KW - 1) + t) * 768 + ct * 96];
            #pragma unroll
            for (int cb = 0; cb < 4; cb++) {
                #pragma unroll
                for (int j = 0; j < 2; j++) {
                    int c = cb * 8 + tid2 * 2 + j;
                    float gir, giz, gin;
                    if (valid) { gir = gx[c]; giz = gx[32 + c]; gin = gx[64 + c]; }
                    else {
                        gir = b_ih[ct * 32 + c];
                        giz = b_ih[256 + ct * 32 + c];
                        gin = b_ih[512 + ct * 32 + c];
                    }
                    float r = 1.f / (1.f + __expf(-(gir + acc[cb][i * 2 + j] +
                                                    b_hh[ct * 32 + c])));
                    float z = 1.f / (1.f + __expf(-(giz + acc[4 + cb][i * 2 + j] +
                                                    b_hh[256 + ct * 32 + c])));
                    float n = tanhf(fmaf(r, acc[8 + cb][i * 2 + j] +
                                            b_hh[512 + ct * 32 + c], gin));
                    float hp = unpackh(A[(size_t)m * 256 + ct * 32 + c]);
                    float h = fmaf(z, hp - n, n);    // (1-z)*n + z*hprev
                    if (t == KW - 1)
                        fout[(size_t)m * 256 + ct * 32 + c] = h;
                    else
                        Hdst[(size_t)m * 256 + ct * 32 + c] = packh(h);
                }
            }
        }
    }
}

// ---------------------------------------------------------------------------
extern "C" void kernel_launch(void* const* d_in, const int* in_sizes, int n_in,
                              void* d_out, int out_size)
{
    const float* x    = (const float*)d_in[0];
    const float* W_ih = (const float*)d_in[1];
    const float* W_hh = (const float*)d_in[2];
    const float* b_ih = (const float*)d_in[3];
    const float* b_hh = (const float*)d_in[4];
    float* out = (float*)d_out;

    cudaFuncSetAttribute(gemm_fused,
                         cudaFuncAttributeMaxDynamicSharedMemorySize, 57344);

    pack_x_kernel<<<MM * 256 / 256, 256>>>(x);
    pack_w_kernel<<<8 * 96 * 512 / 256, 256>>>(W_ih, W_hh);

    // Gx = x @ W_ih^T + b_ih (gate-major packed columns)
    gemm_fused<<<dim3(8, MM / 128), 256, 57344>>>(0, 0, 0, 0, b_ih, b_hh, nullptr);

    // step 0 (h = 0): elementwise
    step0_kernel<<<MM, 256>>>(b_ih, b_hh);

    // steps 1..15: fused GEMM + GRU update; last writes d_out
    for (int t = 1; t < KW; t++) {
        gemm_fused<<<dim3(8, MM / 128), 256, 57344>>>(
            1, t, (t - 1) & 1, t & 1, b_ih, b_hh, (t == KW - 1) ? out : nullptr);
    }
}